// round 3
// baseline (speedup 1.0000x reference)
#include <cuda_runtime.h>
#include <math.h>

// Problem constants (from reference)
#define L_A        128
#define B_DIM      64
#define NUM_PAIRS  (L_A * B_DIM)   // 8192
#define NUM_RULES  256
#define NUM_TOKENS 32000
#define MAX_QUERY  512
#define EPS_VAL    1e-7f

#define BLOCKS   32
#define THREADS  256   // BLOCKS * THREADS == NUM_PAIRS

__device__ float        g_partials[BLOCKS];
__device__ unsigned int g_count = 0;   // reset to 0 by the last block each run

__device__ __forceinline__ float gather_or_zero(const float* __restrict__ p,
                                                int pair, int stride, int idx) {
    // idx == -1 contributes 0 (matches reference _gather_prob)
    int safe = idx < 0 ? 0 : idx;
    float v = __ldg(p + (long long)pair * stride + safe);
    return (idx == -1) ? 0.0f : v;
}

__global__ void loss_fused_kernel(const float* __restrict__ rule_prob,
                                  const float* __restrict__ token_prob,
                                  const float* __restrict__ copy_prob,
                                  const int*   __restrict__ gt_rule,
                                  const int*   __restrict__ gt_token,
                                  const int*   __restrict__ gt_copy,
                                  const float* __restrict__ mask,
                                  float*       __restrict__ out) {
    int pair = blockIdx.x * blockDim.x + threadIdx.x;   // 0..8191

    // Indices first (independent), then all 3 gathers (independent -> MLP >= 3)
    int r = gt_rule[pair];
    int t = gt_token[pair];
    int c = gt_copy[pair];
    float m = mask[pair];

    float prob = gather_or_zero(rule_prob,  pair, NUM_RULES,  r)
               + gather_or_zero(token_prob, pair, NUM_TOKENS, t)
               + gather_or_zero(copy_prob,  pair, MAX_QUERY,  c);

    // reference: prob = prob + (prob < EPS) * EPS   (an add, not a clamp)
    if (prob < EPS_VAL) prob += EPS_VAL;

    float loss = -logf(prob) * m;

    // --- block reduction: warp shuffle + shared ---
    #pragma unroll
    for (int off = 16; off > 0; off >>= 1)
        loss += __shfl_xor_sync(0xFFFFFFFFu, loss, off);

    __shared__ float warp_sums[THREADS / 32];
    int lane = threadIdx.x & 31;
    int wid  = threadIdx.x >> 5;
    if (lane == 0) warp_sums[wid] = loss;
    __syncthreads();

    if (wid == 0) {
        float v = (lane < THREADS / 32) ? warp_sums[lane] : 0.0f;
        #pragma unroll
        for (int off = 16; off > 0; off >>= 1)
            v += __shfl_xor_sync(0xFFFFFFFFu, v, off);

        // Publish this block's partial, then count completion.
        if (lane == 0) {
            g_partials[blockIdx.x] = v;
            __threadfence();
        }
        __syncwarp();

        unsigned int is_last = 0;
        if (lane == 0)
            is_last = (atomicAdd(&g_count, 1u) == (unsigned)(BLOCKS - 1));
        is_last = __shfl_sync(0xFFFFFFFFu, is_last, 0);

        if (is_last) {
            __threadfence();  // make all blocks' partial writes visible
            // BLOCKS == 32 == warp size: one partial per lane, volatile to bypass L1
            float x = *((volatile float*)&g_partials[lane]);
            #pragma unroll
            for (int off = 16; off > 0; off >>= 1)
                x += __shfl_xor_sync(0xFFFFFFFFu, x, off);
            if (lane == 0) {
                out[0] = x * (1.0f / (float)B_DIM);
                g_count = 0;          // restore state for next graph replay
                __threadfence();
            }
        }
    }
}

extern "C" void kernel_launch(void* const* d_in, const int* in_sizes, int n_in,
                              void* d_out, int out_size) {
    const float* rule_prob  = (const float*)d_in[0];
    const float* token_prob = (const float*)d_in[1];
    const float* copy_prob  = (const float*)d_in[2];
    const int*   gt_rule    = (const int*)  d_in[3];
    const int*   gt_token   = (const int*)  d_in[4];
    const int*   gt_copy    = (const int*)  d_in[5];
    const float* mask       = (const float*)d_in[6];
    float* out = (float*)d_out;

    loss_fused_kernel<<<BLOCKS, THREADS>>>(rule_prob, token_prob, copy_prob,
                                           gt_rule, gt_token, gt_copy, mask, out);
}

// round 4
// speedup vs baseline: 1.2885x; 1.2885x over previous
#include <cuda_runtime.h>
#include <math.h>

// Problem constants (from reference)
#define L_A        128
#define B_DIM      64
#define NUM_PAIRS  (L_A * B_DIM)   // 8192
#define NUM_RULES  256
#define NUM_TOKENS 32000
#define MAX_QUERY  512
#define EPS_VAL    1e-7f

#define BLOCKS   64
#define THREADS  128   // BLOCKS * THREADS == NUM_PAIRS

__device__ float g_partials[BLOCKS];

__device__ __forceinline__ float gather_or_zero(const float* __restrict__ p,
                                                int pair, int stride, int idx) {
    // idx == -1 contributes 0 (matches reference _gather_prob)
    int safe = idx < 0 ? 0 : idx;
    float v = __ldg(p + (long long)pair * stride + safe);
    return (idx == -1) ? 0.0f : v;
}

__global__ void loss_gather_kernel(const float* __restrict__ rule_prob,
                                   const float* __restrict__ token_prob,
                                   const float* __restrict__ copy_prob,
                                   const int*   __restrict__ gt_rule,
                                   const int*   __restrict__ gt_token,
                                   const int*   __restrict__ gt_copy,
                                   const float* __restrict__ mask) {
    // PDL: let the dependent (final) kernel begin its launch immediately;
    // its griddepcontrol.wait still blocks until our memory flush completes.
    asm volatile("griddepcontrol.launch_dependents;" ::: "memory");

    int pair = blockIdx.x * blockDim.x + threadIdx.x;   // 0..8191

    // Indices first (independent), then all 3 gathers (independent -> MLP >= 3)
    int r = gt_rule[pair];
    int t = gt_token[pair];
    int c = gt_copy[pair];
    float m = mask[pair];

    float prob = gather_or_zero(rule_prob,  pair, NUM_RULES,  r)
               + gather_or_zero(token_prob, pair, NUM_TOKENS, t)
               + gather_or_zero(copy_prob,  pair, MAX_QUERY,  c);

    // reference: prob = prob + (prob < EPS) * EPS   (an add, not a clamp)
    if (prob < EPS_VAL) prob += EPS_VAL;

    float loss = -logf(prob) * m;

    // --- block reduction: warp shuffle + shared ---
    #pragma unroll
    for (int off = 16; off > 0; off >>= 1)
        loss += __shfl_xor_sync(0xFFFFFFFFu, loss, off);

    __shared__ float warp_sums[THREADS / 32];
    int lane = threadIdx.x & 31;
    int wid  = threadIdx.x >> 5;
    if (lane == 0) warp_sums[wid] = loss;
    __syncthreads();

    if (wid == 0) {
        float v = (lane < THREADS / 32) ? warp_sums[lane] : 0.0f;
        #pragma unroll
        for (int off = 16; off > 0; off >>= 1)
            v += __shfl_xor_sync(0xFFFFFFFFu, v, off);
        if (lane == 0) g_partials[blockIdx.x] = v;
    }
}

__global__ void loss_final_kernel(float* __restrict__ out) {
    // PDL: wait until the primary grid's memory writes are visible.
    asm volatile("griddepcontrol.wait;" ::: "memory");

    int lane = threadIdx.x;   // 32 threads; BLOCKS == 64 -> 2 partials per lane
    float v = g_partials[lane] + g_partials[lane + 32];
    #pragma unroll
    for (int off = 16; off > 0; off >>= 1)
        v += __shfl_xor_sync(0xFFFFFFFFu, v, off);
    if (lane == 0) out[0] = v * (1.0f / (float)B_DIM);
}

extern "C" void kernel_launch(void* const* d_in, const int* in_sizes, int n_in,
                              void* d_out, int out_size) {
    const float* rule_prob  = (const float*)d_in[0];
    const float* token_prob = (const float*)d_in[1];
    const float* copy_prob  = (const float*)d_in[2];
    const int*   gt_rule    = (const int*)  d_in[3];
    const int*   gt_token   = (const int*)  d_in[4];
    const int*   gt_copy    = (const int*)  d_in[5];
    const float* mask       = (const float*)d_in[6];
    float* out = (float*)d_out;

    loss_gather_kernel<<<BLOCKS, THREADS>>>(rule_prob, token_prob, copy_prob,
                                            gt_rule, gt_token, gt_copy, mask);

    // Launch the final reduction with Programmatic Dependent Launch so its
    // launch latency overlaps the gather kernel's execution.
    cudaLaunchAttribute attrs[1];
    attrs[0].id = cudaLaunchAttributeProgrammaticStreamSerialization;
    attrs[0].val.programmaticStreamSerializationAllowed = 1;

    cudaLaunchConfig_t cfg = {};
    cfg.gridDim  = dim3(1, 1, 1);
    cfg.blockDim = dim3(32, 1, 1);
    cfg.dynamicSmemBytes = 0;
    cfg.stream = 0;           // legacy default stream (same one the harness captures)
    cfg.attrs = attrs;
    cfg.numAttrs = 1;

    cudaError_t err = cudaLaunchKernelEx(&cfg, loss_final_kernel, out);
    if (err != cudaSuccess) {
        // Fallback: plain serialized launch (still correct, no PDL overlap).
        loss_final_kernel<<<1, 32>>>(out);
    }
}

// round 5
// speedup vs baseline: 1.2947x; 1.0048x over previous
#include <cuda_runtime.h>
#include <math.h>

// Problem constants (from reference)
#define L_A        128
#define B_DIM      64
#define NUM_PAIRS  (L_A * B_DIM)   // 8192
#define NUM_RULES  256
#define NUM_TOKENS 32000
#define MAX_QUERY  512
#define EPS_VAL    1e-7f

#define BLOCKS   128
#define THREADS  64    // BLOCKS * THREADS == NUM_PAIRS

__device__ float g_partials[BLOCKS];

__device__ __forceinline__ float gather_or_zero(const float* __restrict__ p,
                                                int pair, int stride, int idx) {
    // idx == -1 contributes 0 (matches reference _gather_prob)
    int safe = idx < 0 ? 0 : idx;
    float v = __ldg(p + (long long)pair * stride + safe);
    return (idx == -1) ? 0.0f : v;
}

__global__ void __launch_bounds__(THREADS, 1)
loss_gather_kernel(const float* __restrict__ rule_prob,
                   const float* __restrict__ token_prob,
                   const float* __restrict__ copy_prob,
                   const int*   __restrict__ gt_rule,
                   const int*   __restrict__ gt_token,
                   const int*   __restrict__ gt_copy,
                   const float* __restrict__ mask) {
    // PDL: allow the dependent (final) kernel to begin its launch now; its
    // griddepcontrol.wait still gates on this grid's full memory flush.
    asm volatile("griddepcontrol.launch_dependents;" ::: "memory");

    int pair = blockIdx.x * blockDim.x + threadIdx.x;   // 0..8191

    // Indices first (independent), then all 3 gathers (independent -> MLP >= 3)
    int r = gt_rule[pair];
    int t = gt_token[pair];
    int c = gt_copy[pair];
    float m = mask[pair];

    float prob = gather_or_zero(rule_prob,  pair, NUM_RULES,  r)
               + gather_or_zero(token_prob, pair, NUM_TOKENS, t)
               + gather_or_zero(copy_prob,  pair, MAX_QUERY,  c);

    // reference: prob = prob + (prob < EPS) * EPS   (an add, not a clamp)
    if (prob < EPS_VAL) prob += EPS_VAL;

    float loss = -logf(prob) * m;

    // --- block reduction: warp shuffle, then 2-warp combine via shared ---
    #pragma unroll
    for (int off = 16; off > 0; off >>= 1)
        loss += __shfl_xor_sync(0xFFFFFFFFu, loss, off);

    __shared__ float warp_sums[THREADS / 32];   // 2
    int lane = threadIdx.x & 31;
    int wid  = threadIdx.x >> 5;
    if (lane == 0) warp_sums[wid] = loss;
    __syncthreads();

    if (threadIdx.x == 0)
        g_partials[blockIdx.x] = warp_sums[0] + warp_sums[1];
}

__global__ void loss_final_kernel(float* __restrict__ out) {
    // PDL: wait until the primary grid's memory writes are visible.
    asm volatile("griddepcontrol.wait;" ::: "memory");

    int lane = threadIdx.x;   // 32 threads; 128 partials -> one float4 per lane
    float4 p = *((const float4*)g_partials + lane);
    float v = (p.x + p.y) + (p.z + p.w);
    #pragma unroll
    for (int off = 16; off > 0; off >>= 1)
        v += __shfl_xor_sync(0xFFFFFFFFu, v, off);
    if (lane == 0) out[0] = v * (1.0f / (float)B_DIM);
}

extern "C" void kernel_launch(void* const* d_in, const int* in_sizes, int n_in,
                              void* d_out, int out_size) {
    const float* rule_prob  = (const float*)d_in[0];
    const float* token_prob = (const float*)d_in[1];
    const float* copy_prob  = (const float*)d_in[2];
    const int*   gt_rule    = (const int*)  d_in[3];
    const int*   gt_token   = (const int*)  d_in[4];
    const int*   gt_copy    = (const int*)  d_in[5];
    const float* mask       = (const float*)d_in[6];
    float* out = (float*)d_out;

    loss_gather_kernel<<<BLOCKS, THREADS>>>(rule_prob, token_prob, copy_prob,
                                            gt_rule, gt_token, gt_copy, mask);

    // Final reduction with Programmatic Dependent Launch: its launch latency
    // overlaps the gather kernel's execution.
    cudaLaunchAttribute attrs[1];
    attrs[0].id = cudaLaunchAttributeProgrammaticStreamSerialization;
    attrs[0].val.programmaticStreamSerializationAllowed = 1;

    cudaLaunchConfig_t cfg = {};
    cfg.gridDim  = dim3(1, 1, 1);
    cfg.blockDim = dim3(32, 1, 1);
    cfg.dynamicSmemBytes = 0;
    cfg.stream = 0;           // legacy default stream (the one the harness captures)
    cfg.attrs = attrs;
    cfg.numAttrs = 1;

    cudaError_t err = cudaLaunchKernelEx(&cfg, loss_final_kernel, out);
    if (err != cudaSuccess) {
        // Fallback: plain serialized launch (still correct, no PDL overlap).
        loss_final_kernel<<<1, 32>>>(out);
    }
}